// round 6
// baseline (speedup 1.0000x reference)
#include <cuda_runtime.h>

#define N_NODES 50000
#define N_EDGES 800000
#define IN_FEAT 256
#define DIM_H 64
#define DIM_OUT 64

// scratch (static device globals; no allocations allowed)
__device__ float g_h_src[N_NODES * DIM_H];   // 12.8 MB
__device__ float g_a_src[N_NODES];
__device__ float g_a_dst[N_NODES];
__device__ float g_agg[N_NODES * DIM_H];     // 12.8 MB
__device__ float g_wa_src[IN_FEAT];
__device__ float g_wa_dst[IN_FEAT];
__device__ int   g_cnt[N_NODES];
__device__ int   g_rowptr[N_NODES + 1];
__device__ int   g_cursor[N_NODES];
__device__ float2 g_rec[N_EDGES];            // {src (bitcast int), eexp}
__device__ int   g_is64;

// ---------------------------------------------------------------------------
__device__ __forceinline__ int load_src(const int* e32, int i, int is64) {
    return is64 ? e32[2 * i] : e32[i];
}
__device__ __forceinline__ int load_dst(const int* e32, int i, int is64) {
    return is64 ? e32[2 * (N_EDGES + i)] : e32[N_EDGES + i];
}

// detect edge dtype (thread 0) + wa = W@att (256 threads)
__global__ void prep_kernel(const int* __restrict__ e32,
                            const float* __restrict__ Wsrc,
                            const float* __restrict__ Wdst,
                            const float* __restrict__ atts,
                            const float* __restrict__ attd) {
    int k = threadIdx.x;
    if (k == 0) {
        const long long* e64 = (const long long*)e32;
        int ok64 = 1;
        for (int i = 0; i < 256; i++) {
            long long v = e64[i];
            if (v < 0 || v >= N_NODES) { ok64 = 0; break; }
        }
        g_is64 = ok64;
    }
    if (k < IN_FEAT) {
        float s = 0.f, d = 0.f;
#pragma unroll
        for (int j = 0; j < DIM_H; j++) {
            s += Wsrc[k * DIM_H + j] * atts[j];
            d += Wdst[k * DIM_H + j] * attd[j];
        }
        g_wa_src[k] = s;
        g_wa_dst[k] = d;
    }
}

// ---------------------------------------------------------------------------
// h_src = x @ W_src ; a_src = x @ wa_src ; a_dst = x @ wa_dst
__global__ __launch_bounds__(128, 4) void proj_kernel(const float* __restrict__ x,
                                                      const float* __restrict__ Wsrc) {
    __shared__ float Xs[32][129];
    __shared__ __align__(16) float Ws_s[32][64];
    __shared__ float was_s[32], wad_s[32];

    int tx = threadIdx.x;
    int node0 = blockIdx.x * 128;
    int fg = (tx >> 2) & 7;
    int ng = (tx & 3) + ((tx >> 5) << 2);

    float acc[8][8];
#pragma unroll
    for (int i = 0; i < 8; i++)
#pragma unroll
        for (int j = 0; j < 8; j++) acc[i][j] = 0.f;
    float as = 0.f, ad = 0.f;

    for (int kc = 0; kc < IN_FEAT / 32; kc++) {
        __syncthreads();
#pragma unroll
        for (int i = tx; i < 1024; i += 128) {
            int nd = i >> 3, kq = i & 7;
            int row = node0 + nd; if (row >= N_NODES) row = N_NODES - 1;
            float4 v = ((const float4*)(x + (size_t)row * IN_FEAT + kc * 32))[kq];
            Xs[kq * 4 + 0][nd] = v.x;
            Xs[kq * 4 + 1][nd] = v.y;
            Xs[kq * 4 + 2][nd] = v.z;
            Xs[kq * 4 + 3][nd] = v.w;
        }
        const float4* w4 = (const float4*)(Wsrc + kc * 32 * 64);
        float4* ws4 = (float4*)&Ws_s[0][0];
#pragma unroll
        for (int i = tx; i < 512; i += 128) ws4[i] = w4[i];
        if (tx < 32) was_s[tx] = g_wa_src[kc * 32 + tx];
        else if (tx < 64) wad_s[tx - 32] = g_wa_dst[kc * 32 + tx - 32];
        __syncthreads();

#pragma unroll
        for (int k = 0; k < 32; k++) {
            float xv = Xs[k][tx];
            as += xv * was_s[k];
            ad += xv * wad_s[k];
        }

#pragma unroll
        for (int k = 0; k < 32; k++) {
            float xv[8];
#pragma unroll
            for (int i = 0; i < 8; i++) xv[i] = Xs[k][ng * 8 + i];
            float4 w0 = ((const float4*)&Ws_s[k][0])[fg * 2 + 0];
            float4 w1 = ((const float4*)&Ws_s[k][0])[fg * 2 + 1];
            float wv[8] = {w0.x, w0.y, w0.z, w0.w, w1.x, w1.y, w1.z, w1.w};
#pragma unroll
            for (int i = 0; i < 8; i++)
#pragma unroll
                for (int j = 0; j < 8; j++) acc[i][j] += xv[i] * wv[j];
        }
    }

    int nmax = N_NODES - node0;
#pragma unroll
    for (int i = 0; i < 8; i++) {
        int nd = ng * 8 + i;
        if (nd < nmax) {
            float4* o = (float4*)(g_h_src + (size_t)(node0 + nd) * DIM_H + fg * 8);
            float4 v0 = {acc[i][0], acc[i][1], acc[i][2], acc[i][3]};
            float4 v1 = {acc[i][4], acc[i][5], acc[i][6], acc[i][7]};
            o[0] = v0; o[1] = v1;
        }
    }
    if (tx < nmax) {
        g_a_src[node0 + tx] = as;
        g_a_dst[node0 + tx] = ad;
    }
}

// ---------------------------------------------------------------------------
// pass 1: histogram of dst
__global__ void hist_kernel(const int* __restrict__ e32) {
    int i = blockIdx.x * blockDim.x + threadIdx.x;
    if (i >= N_EDGES) return;
    int d = load_dst(e32, i, g_is64);
    atomicAdd(&g_cnt[d], 1);
}

// pass 2: exclusive scan of cnt -> rowptr (single block, 1024 threads)
__global__ __launch_bounds__(1024) void scan_kernel() {
    __shared__ int sums[1024];
    int t = threadIdx.x;
    const int PER = (N_NODES + 1023) / 1024;   // 49
    int base = t * PER;
    int s = 0;
    for (int i = 0; i < PER; i++) {
        int idx = base + i;
        if (idx < N_NODES) s += g_cnt[idx];
    }
    sums[t] = s;
    __syncthreads();
    // Hillis-Steele inclusive scan
    for (int off = 1; off < 1024; off <<= 1) {
        int v = (t >= off) ? sums[t - off] : 0;
        __syncthreads();
        sums[t] += v;
        __syncthreads();
    }
    int run = (t == 0) ? 0 : sums[t - 1];   // exclusive prefix for this chunk
    for (int i = 0; i < PER; i++) {
        int idx = base + i;
        if (idx < N_NODES) {
            g_rowptr[idx] = run;
            run += g_cnt[idx];
        }
    }
    if (t == 1023) g_rowptr[N_NODES] = run;
}

// pass 3: bin edges into CSR order; record = {src, exp(leaky_relu(e))}
__global__ void bin_kernel(const int* __restrict__ e32) {
    int i = blockIdx.x * blockDim.x + threadIdx.x;
    if (i >= N_EDGES) return;
    int is64 = g_is64;
    int s = load_src(e32, i, is64);
    int d = load_dst(e32, i, is64);
    float e = g_a_src[s] + g_a_dst[d];
    e = e > 0.f ? e : 0.2f * e;
    float ex = __expf(e);
    int pos = atomicAdd(&g_cursor[d], 1);
    float2 rec = {__int_as_float(s), ex};
    g_rec[g_rowptr[d] + pos] = rec;
}

// pass 4: per-dst gather reduction (no atomics):
// agg[d] = (sum_j eexp_j * h_src[s_j]) / (sum_j eexp_j)
__global__ __launch_bounds__(256) void gather_kernel() {
    int node = (blockIdx.x * blockDim.x + threadIdx.x) >> 5;
    int lane = threadIdx.x & 31;
    if (node >= N_NODES) return;
    int beg = g_rowptr[node];
    int end = g_rowptr[node + 1];

    float acc0 = 0.f, acc1 = 0.f, denom = 0.f;
    for (int base = beg; base < end; base += 32) {
        int n = min(32, end - base);
        float2 rec = (lane < n) ? g_rec[base + lane] : make_float2(0.f, 0.f);
        for (int j = 0; j < n; j++) {
            float ex = __shfl_sync(0xFFFFFFFFu, rec.y, j);
            int   s  = __shfl_sync(0xFFFFFFFFu, __float_as_int(rec.x), j);
            const float* hp = g_h_src + (size_t)s * DIM_H;
            denom += ex;
            acc0 += ex * hp[lane];
            acc1 += ex * hp[32 + lane];
        }
    }
    float inv = (end > beg) ? (1.f / denom) : 0.f;
    g_agg[(size_t)node * DIM_H + lane]      = acc0 * inv;
    g_agg[(size_t)node * DIM_H + 32 + lane] = acc1 * inv;
}

// ---------------------------------------------------------------------------
// out = relu(agg + bias_conv) @ W_lin + b_lin
__global__ __launch_bounds__(128, 4) void out_kernel(const float* __restrict__ Wlin,
                                                     const float* __restrict__ bias_conv,
                                                     const float* __restrict__ blin,
                                                     float* __restrict__ out) {
    __shared__ float Hs[32][129];
    __shared__ __align__(16) float Ws_s[32][64];
    __shared__ float bc_s[32], bl_s[64];

    int tx = threadIdx.x;
    int node0 = blockIdx.x * 128;
    int fg = (tx >> 2) & 7;
    int ng = (tx & 3) + ((tx >> 5) << 2);

    if (tx < 64) bl_s[tx] = blin[tx];

    float acc[8][8];
#pragma unroll
    for (int i = 0; i < 8; i++)
#pragma unroll
        for (int j = 0; j < 8; j++) acc[i][j] = 0.f;

    for (int kc = 0; kc < DIM_H / 32; kc++) {
        __syncthreads();
        if (tx < 32) bc_s[tx] = bias_conv[kc * 32 + tx];
        __syncthreads();
#pragma unroll
        for (int i = tx; i < 1024; i += 128) {
            int nd = i >> 3, kq = i & 7;
            int row = node0 + nd; if (row >= N_NODES) row = N_NODES - 1;
            float4 v = ((const float4*)(g_agg + (size_t)row * DIM_H + kc * 32))[kq];
            float h0 = v.x + bc_s[kq * 4 + 0];
            float h1 = v.y + bc_s[kq * 4 + 1];
            float h2 = v.z + bc_s[kq * 4 + 2];
            float h3 = v.w + bc_s[kq * 4 + 3];
            Hs[kq * 4 + 0][nd] = h0 > 0.f ? h0 : 0.f;
            Hs[kq * 4 + 1][nd] = h1 > 0.f ? h1 : 0.f;
            Hs[kq * 4 + 2][nd] = h2 > 0.f ? h2 : 0.f;
            Hs[kq * 4 + 3][nd] = h3 > 0.f ? h3 : 0.f;
        }
        const float4* w4 = (const float4*)(Wlin + kc * 32 * 64);
        float4* ws4 = (float4*)&Ws_s[0][0];
#pragma unroll
        for (int i = tx; i < 512; i += 128) ws4[i] = w4[i];
        __syncthreads();

#pragma unroll
        for (int k = 0; k < 32; k++) {
            float hv[8];
#pragma unroll
            for (int i = 0; i < 8; i++) hv[i] = Hs[k][ng * 8 + i];
            float4 w0 = ((const float4*)&Ws_s[k][0])[fg * 2 + 0];
            float4 w1 = ((const float4*)&Ws_s[k][0])[fg * 2 + 1];
            float wv[8] = {w0.x, w0.y, w0.z, w0.w, w1.x, w1.y, w1.z, w1.w};
#pragma unroll
            for (int i = 0; i < 8; i++)
#pragma unroll
                for (int j = 0; j < 8; j++) acc[i][j] += hv[i] * wv[j];
        }
    }

    int nmax = N_NODES - node0;
#pragma unroll
    for (int i = 0; i < 8; i++) {
        int nd = ng * 8 + i;
        if (nd < nmax) {
            float4* o = (float4*)(out + (size_t)(node0 + nd) * DIM_OUT + fg * 8);
            float4 v0 = {acc[i][0] + bl_s[fg * 8 + 0], acc[i][1] + bl_s[fg * 8 + 1],
                         acc[i][2] + bl_s[fg * 8 + 2], acc[i][3] + bl_s[fg * 8 + 3]};
            float4 v1 = {acc[i][4] + bl_s[fg * 8 + 4], acc[i][5] + bl_s[fg * 8 + 5],
                         acc[i][6] + bl_s[fg * 8 + 6], acc[i][7] + bl_s[fg * 8 + 7]};
            o[0] = v0; o[1] = v1;
        }
    }
}

// ---------------------------------------------------------------------------
extern "C" void kernel_launch(void* const* d_in, const int* in_sizes, int n_in,
                              void* d_out, int out_size) {
    const float* x     = (const float*)d_in[0];
    const int*   e32   = (const int*)d_in[1];
    const float* Wsrc  = (const float*)d_in[2];
    const float* Wdst  = (const float*)d_in[3];
    const float* atts  = (const float*)d_in[4];
    const float* attd  = (const float*)d_in[5];
    const float* bconv = (const float*)d_in[6];
    const float* Wlin  = (const float*)d_in[7];
    const float* blin  = (const float*)d_in[8];
    float*       out   = (float*)d_out;

    void* cnt_ptr = nullptr;
    void* cur_ptr = nullptr;
    cudaGetSymbolAddress(&cnt_ptr, g_cnt);
    cudaGetSymbolAddress(&cur_ptr, g_cursor);
    cudaMemsetAsync(cnt_ptr, 0, (size_t)N_NODES * sizeof(int), 0);
    cudaMemsetAsync(cur_ptr, 0, (size_t)N_NODES * sizeof(int), 0);

    const int NODE_BLOCKS = (N_NODES + 127) / 128;   // 391
    const int EDGE_BLOCKS = (N_EDGES + 255) / 256;   // 3125

    prep_kernel<<<1, 256>>>(e32, Wsrc, Wdst, atts, attd);
    hist_kernel<<<EDGE_BLOCKS, 256>>>(e32);
    proj_kernel<<<NODE_BLOCKS, 128>>>(x, Wsrc);      // overlap-friendly order
    scan_kernel<<<1, 1024>>>();
    bin_kernel<<<EDGE_BLOCKS, 256>>>(e32);
    gather_kernel<<<(N_NODES * 32 + 255) / 256, 256>>>();
    out_kernel<<<NODE_BLOCKS, 128>>>(Wlin, bconv, blin, out);
}

// round 7
// speedup vs baseline: 1.2910x; 1.2910x over previous
#include <cuda_runtime.h>

#define N_NODES 50000
#define N_EDGES 800000
#define IN_FEAT 256
#define DIM_H 64
#define DIM_OUT 64

#define SCAN_B 1024
#define NB_SCAN ((N_NODES + SCAN_B - 1) / SCAN_B)   // 49

// scratch (static device globals; no allocations allowed)
__device__ float g_h_src[N_NODES * DIM_H];   // 12.8 MB
__device__ float g_a_src[N_NODES];
__device__ float g_a_dst[N_NODES];
__device__ float g_agg[N_NODES * DIM_H];     // 12.8 MB
__device__ float g_wa_src[IN_FEAT];
__device__ float g_wa_dst[IN_FEAT];
__device__ int   g_cnt[N_NODES];
__device__ int   g_rowptr[N_NODES + 1];
__device__ int   g_pos[N_EDGES];             // within-segment slot from hist
__device__ int   g_bsum[NB_SCAN];
__device__ int   g_boff[NB_SCAN];
__device__ float2 g_rec[N_EDGES];            // {src (bitcast int), eexp}
__device__ int   g_is64;

// ---------------------------------------------------------------------------
__device__ __forceinline__ int load_src(const int* e32, int i, int is64) {
    return is64 ? e32[2 * i] : e32[i];
}
__device__ __forceinline__ int load_dst(const int* e32, int i, int is64) {
    return is64 ? e32[2 * (N_EDGES + i)] : e32[N_EDGES + i];
}

// detect edge dtype (thread 0) + wa = W@att (256 threads)
__global__ void prep_kernel(const int* __restrict__ e32,
                            const float* __restrict__ Wsrc,
                            const float* __restrict__ Wdst,
                            const float* __restrict__ atts,
                            const float* __restrict__ attd) {
    int k = threadIdx.x;
    if (k == 0) {
        const long long* e64 = (const long long*)e32;
        int ok64 = 1;
        for (int i = 0; i < 256; i++) {
            long long v = e64[i];
            if (v < 0 || v >= N_NODES) { ok64 = 0; break; }
        }
        g_is64 = ok64;
    }
    if (k < IN_FEAT) {
        float s = 0.f, d = 0.f;
#pragma unroll
        for (int j = 0; j < DIM_H; j++) {
            s += Wsrc[k * DIM_H + j] * atts[j];
            d += Wdst[k * DIM_H + j] * attd[j];
        }
        g_wa_src[k] = s;
        g_wa_dst[k] = d;
    }
}

// ---------------------------------------------------------------------------
// h_src = x @ W_src ; a_src = x @ wa_src ; a_dst = x @ wa_dst
__global__ __launch_bounds__(128, 4) void proj_kernel(const float* __restrict__ x,
                                                      const float* __restrict__ Wsrc) {
    __shared__ float Xs[32][129];
    __shared__ __align__(16) float Ws_s[32][64];
    __shared__ float was_s[32], wad_s[32];

    int tx = threadIdx.x;
    int node0 = blockIdx.x * 128;
    int fg = (tx >> 2) & 7;
    int ng = (tx & 3) + ((tx >> 5) << 2);

    float acc[8][8];
#pragma unroll
    for (int i = 0; i < 8; i++)
#pragma unroll
        for (int j = 0; j < 8; j++) acc[i][j] = 0.f;
    float as = 0.f, ad = 0.f;

    for (int kc = 0; kc < IN_FEAT / 32; kc++) {
        __syncthreads();
#pragma unroll
        for (int i = tx; i < 1024; i += 128) {
            int nd = i >> 3, kq = i & 7;
            int row = node0 + nd; if (row >= N_NODES) row = N_NODES - 1;
            float4 v = ((const float4*)(x + (size_t)row * IN_FEAT + kc * 32))[kq];
            Xs[kq * 4 + 0][nd] = v.x;
            Xs[kq * 4 + 1][nd] = v.y;
            Xs[kq * 4 + 2][nd] = v.z;
            Xs[kq * 4 + 3][nd] = v.w;
        }
        const float4* w4 = (const float4*)(Wsrc + kc * 32 * 64);
        float4* ws4 = (float4*)&Ws_s[0][0];
#pragma unroll
        for (int i = tx; i < 512; i += 128) ws4[i] = w4[i];
        if (tx < 32) was_s[tx] = g_wa_src[kc * 32 + tx];
        else if (tx < 64) wad_s[tx - 32] = g_wa_dst[kc * 32 + tx - 32];
        __syncthreads();

#pragma unroll
        for (int k = 0; k < 32; k++) {
            float xv = Xs[k][tx];
            as += xv * was_s[k];
            ad += xv * wad_s[k];
        }

#pragma unroll
        for (int k = 0; k < 32; k++) {
            float xv[8];
#pragma unroll
            for (int i = 0; i < 8; i++) xv[i] = Xs[k][ng * 8 + i];
            float4 w0 = ((const float4*)&Ws_s[k][0])[fg * 2 + 0];
            float4 w1 = ((const float4*)&Ws_s[k][0])[fg * 2 + 1];
            float wv[8] = {w0.x, w0.y, w0.z, w0.w, w1.x, w1.y, w1.z, w1.w};
#pragma unroll
            for (int i = 0; i < 8; i++)
#pragma unroll
                for (int j = 0; j < 8; j++) acc[i][j] += xv[i] * wv[j];
        }
    }

    int nmax = N_NODES - node0;
#pragma unroll
    for (int i = 0; i < 8; i++) {
        int nd = ng * 8 + i;
        if (nd < nmax) {
            float4* o = (float4*)(g_h_src + (size_t)(node0 + nd) * DIM_H + fg * 8);
            float4 v0 = {acc[i][0], acc[i][1], acc[i][2], acc[i][3]};
            float4 v1 = {acc[i][4], acc[i][5], acc[i][6], acc[i][7]};
            o[0] = v0; o[1] = v1;
        }
    }
    if (tx < nmax) {
        g_a_src[node0 + tx] = as;
        g_a_dst[node0 + tx] = ad;
    }
}

// ---------------------------------------------------------------------------
// pass 1: histogram of dst; atomic return value = within-segment slot
__global__ void hist_kernel(const int* __restrict__ e32) {
    int i = blockIdx.x * blockDim.x + threadIdx.x;
    if (i >= N_EDGES) return;
    int d = load_dst(e32, i, g_is64);
    g_pos[i] = atomicAdd(&g_cnt[d], 1);
}

// pass 2a: per-block exclusive scan (coalesced) + block sums
__global__ __launch_bounds__(SCAN_B) void scan_up_kernel() {
    __shared__ int sm[SCAN_B];
    int t = threadIdx.x;
    int idx = blockIdx.x * SCAN_B + t;
    int v = (idx < N_NODES) ? g_cnt[idx] : 0;
    sm[t] = v;
    __syncthreads();
#pragma unroll
    for (int off = 1; off < SCAN_B; off <<= 1) {
        int u = (t >= off) ? sm[t - off] : 0;
        __syncthreads();
        sm[t] += u;
        __syncthreads();
    }
    if (idx < N_NODES) g_rowptr[idx] = sm[t] - v;   // exclusive, block-local
    if (t == SCAN_B - 1) g_bsum[blockIdx.x] = sm[t];
}

// pass 2b: scan the 49 block sums (1 tiny block)
__global__ __launch_bounds__(64) void scan_mid_kernel() {
    __shared__ int sm[64];
    int t = threadIdx.x;
    int v = (t < NB_SCAN) ? g_bsum[t] : 0;
    sm[t] = v;
    __syncthreads();
#pragma unroll
    for (int off = 1; off < 64; off <<= 1) {
        int u = (t >= off) ? sm[t - off] : 0;
        __syncthreads();
        sm[t] += u;
        __syncthreads();
    }
    if (t < NB_SCAN) g_boff[t] = sm[t] - v;         // exclusive
    if (t == 63) g_rowptr[N_NODES] = sm[t];          // total = N_EDGES
}

// pass 2c: add block offsets (coalesced)
__global__ void scan_add_kernel() {
    int idx = blockIdx.x * SCAN_B + threadIdx.x;
    if (idx < N_NODES) g_rowptr[idx] += g_boff[blockIdx.x];
}

// pass 3: bin edges into CSR order (no atomics; slot from hist)
__global__ void bin_kernel(const int* __restrict__ e32) {
    int i = blockIdx.x * blockDim.x + threadIdx.x;
    if (i >= N_EDGES) return;
    int is64 = g_is64;
    int s = load_src(e32, i, is64);
    int d = load_dst(e32, i, is64);
    float e = g_a_src[s] + g_a_dst[d];
    e = e > 0.f ? e : 0.2f * e;
    float ex = __expf(e);
    float2 rec = {__int_as_float(s), ex};
    g_rec[g_rowptr[d] + g_pos[i]] = rec;
}

// pass 4: per-dst gather reduction (no atomics):
// agg[d] = (sum_j eexp_j * h_src[s_j]) / (sum_j eexp_j)
__global__ __launch_bounds__(256) void gather_kernel() {
    int node = (blockIdx.x * blockDim.x + threadIdx.x) >> 5;
    int lane = threadIdx.x & 31;
    if (node >= N_NODES) return;
    int beg = g_rowptr[node];
    int end = g_rowptr[node + 1];

    float acc0 = 0.f, acc1 = 0.f, denom = 0.f;
    for (int base = beg; base < end; base += 32) {
        int n = min(32, end - base);
        float2 rec = (lane < n) ? g_rec[base + lane] : make_float2(0.f, 0.f);
        for (int j = 0; j < n; j++) {
            float ex = __shfl_sync(0xFFFFFFFFu, rec.y, j);
            int   s  = __shfl_sync(0xFFFFFFFFu, __float_as_int(rec.x), j);
            const float* hp = g_h_src + (size_t)s * DIM_H;
            denom += ex;
            acc0 += ex * hp[lane];
            acc1 += ex * hp[32 + lane];
        }
    }
    float inv = (end > beg) ? (1.f / denom) : 0.f;
    g_agg[(size_t)node * DIM_H + lane]      = acc0 * inv;
    g_agg[(size_t)node * DIM_H + 32 + lane] = acc1 * inv;
}

// ---------------------------------------------------------------------------
// out = relu(agg + bias_conv) @ W_lin + b_lin
__global__ __launch_bounds__(128, 4) void out_kernel(const float* __restrict__ Wlin,
                                                     const float* __restrict__ bias_conv,
                                                     const float* __restrict__ blin,
                                                     float* __restrict__ out) {
    __shared__ float Hs[32][129];
    __shared__ __align__(16) float Ws_s[32][64];
    __shared__ float bc_s[32], bl_s[64];

    int tx = threadIdx.x;
    int node0 = blockIdx.x * 128;
    int fg = (tx >> 2) & 7;
    int ng = (tx & 3) + ((tx >> 5) << 2);

    if (tx < 64) bl_s[tx] = blin[tx];

    float acc[8][8];
#pragma unroll
    for (int i = 0; i < 8; i++)
#pragma unroll
        for (int j = 0; j < 8; j++) acc[i][j] = 0.f;

    for (int kc = 0; kc < DIM_H / 32; kc++) {
        __syncthreads();
        if (tx < 32) bc_s[tx] = bias_conv[kc * 32 + tx];
        __syncthreads();
#pragma unroll
        for (int i = tx; i < 1024; i += 128) {
            int nd = i >> 3, kq = i & 7;
            int row = node0 + nd; if (row >= N_NODES) row = N_NODES - 1;
            float4 v = ((const float4*)(g_agg + (size_t)row * DIM_H + kc * 32))[kq];
            float h0 = v.x + bc_s[kq * 4 + 0];
            float h1 = v.y + bc_s[kq * 4 + 1];
            float h2 = v.z + bc_s[kq * 4 + 2];
            float h3 = v.w + bc_s[kq * 4 + 3];
            Hs[kq * 4 + 0][nd] = h0 > 0.f ? h0 : 0.f;
            Hs[kq * 4 + 1][nd] = h1 > 0.f ? h1 : 0.f;
            Hs[kq * 4 + 2][nd] = h2 > 0.f ? h2 : 0.f;
            Hs[kq * 4 + 3][nd] = h3 > 0.f ? h3 : 0.f;
        }
        const float4* w4 = (const float4*)(Wlin + kc * 32 * 64);
        float4* ws4 = (float4*)&Ws_s[0][0];
#pragma unroll
        for (int i = tx; i < 512; i += 128) ws4[i] = w4[i];
        __syncthreads();

#pragma unroll
        for (int k = 0; k < 32; k++) {
            float hv[8];
#pragma unroll
            for (int i = 0; i < 8; i++) hv[i] = Hs[k][ng * 8 + i];
            float4 w0 = ((const float4*)&Ws_s[k][0])[fg * 2 + 0];
            float4 w1 = ((const float4*)&Ws_s[k][0])[fg * 2 + 1];
            float wv[8] = {w0.x, w0.y, w0.z, w0.w, w1.x, w1.y, w1.z, w1.w};
#pragma unroll
            for (int i = 0; i < 8; i++)
#pragma unroll
                for (int j = 0; j < 8; j++) acc[i][j] += hv[i] * wv[j];
        }
    }

    int nmax = N_NODES - node0;
#pragma unroll
    for (int i = 0; i < 8; i++) {
        int nd = ng * 8 + i;
        if (nd < nmax) {
            float4* o = (float4*)(out + (size_t)(node0 + nd) * DIM_OUT + fg * 8);
            float4 v0 = {acc[i][0] + bl_s[fg * 8 + 0], acc[i][1] + bl_s[fg * 8 + 1],
                         acc[i][2] + bl_s[fg * 8 + 2], acc[i][3] + bl_s[fg * 8 + 3]};
            float4 v1 = {acc[i][4] + bl_s[fg * 8 + 4], acc[i][5] + bl_s[fg * 8 + 5],
                         acc[i][6] + bl_s[fg * 8 + 6], acc[i][7] + bl_s[fg * 8 + 7]};
            o[0] = v0; o[1] = v1;
        }
    }
}

// ---------------------------------------------------------------------------
extern "C" void kernel_launch(void* const* d_in, const int* in_sizes, int n_in,
                              void* d_out, int out_size) {
    const float* x     = (const float*)d_in[0];
    const int*   e32   = (const int*)d_in[1];
    const float* Wsrc  = (const float*)d_in[2];
    const float* Wdst  = (const float*)d_in[3];
    const float* atts  = (const float*)d_in[4];
    const float* attd  = (const float*)d_in[5];
    const float* bconv = (const float*)d_in[6];
    const float* Wlin  = (const float*)d_in[7];
    const float* blin  = (const float*)d_in[8];
    float*       out   = (float*)d_out;

    void* cnt_ptr = nullptr;
    cudaGetSymbolAddress(&cnt_ptr, g_cnt);
    cudaMemsetAsync(cnt_ptr, 0, (size_t)N_NODES * sizeof(int), 0);

    const int NODE_BLOCKS = (N_NODES + 127) / 128;   // 391
    const int EDGE_BLOCKS = (N_EDGES + 255) / 256;   // 3125

    prep_kernel<<<1, 256>>>(e32, Wsrc, Wdst, atts, attd);
    hist_kernel<<<EDGE_BLOCKS, 256>>>(e32);
    scan_up_kernel<<<NB_SCAN, SCAN_B>>>();
    scan_mid_kernel<<<1, 64>>>();
    scan_add_kernel<<<NB_SCAN, SCAN_B>>>();
    proj_kernel<<<NODE_BLOCKS, 128>>>(x, Wsrc);
    bin_kernel<<<EDGE_BLOCKS, 256>>>(e32);
    gather_kernel<<<(N_NODES * 32 + 255) / 256, 256>>>();
    out_kernel<<<NODE_BLOCKS, 128>>>(Wlin, bconv, blin, out);
}

// round 8
// speedup vs baseline: 1.3990x; 1.0837x over previous
#include <cuda_runtime.h>

#define N_NODES 50000
#define N_EDGES 800000
#define IN_FEAT 256
#define DIM_H 64
#define DIM_OUT 64

#define SCAN_B 1024
#define NB_SCAN ((N_NODES + SCAN_B - 1) / SCAN_B)   // 49

// scratch (static device globals; no allocations allowed)
__device__ float g_h_src[N_NODES * DIM_H];   // 12.8 MB
__device__ float g_a_src[N_NODES];
__device__ float g_a_dst[N_NODES];
__device__ float g_agg[N_NODES * DIM_H];     // 12.8 MB
__device__ float g_wa_src[IN_FEAT];
__device__ float g_wa_dst[IN_FEAT];
__device__ int   g_cnt[N_NODES];
__device__ int   g_rowptr[N_NODES + 1];
__device__ int   g_pos[N_EDGES];             // within-segment slot from hist
__device__ int   g_bsum[NB_SCAN];
__device__ float2 g_rec[N_EDGES];            // {src (bitcast int), eexp}
__device__ int   g_is64;

// ---------------------------------------------------------------------------
__device__ __forceinline__ int load_src(const int* e32, int i, int is64) {
    return is64 ? e32[2 * i] : e32[i];
}
__device__ __forceinline__ int load_dst(const int* e32, int i, int is64) {
    return is64 ? e32[2 * (N_EDGES + i)] : e32[N_EDGES + i];
}

// detect edge dtype (thread 0) + wa = W@att (256 threads)
__global__ void prep_kernel(const int* __restrict__ e32,
                            const float* __restrict__ Wsrc,
                            const float* __restrict__ Wdst,
                            const float* __restrict__ atts,
                            const float* __restrict__ attd) {
    int k = threadIdx.x;
    if (k == 0) {
        const long long* e64 = (const long long*)e32;
        int ok64 = 1;
        for (int i = 0; i < 256; i++) {
            long long v = e64[i];
            if (v < 0 || v >= N_NODES) { ok64 = 0; break; }
        }
        g_is64 = ok64;
    }
    if (k < IN_FEAT) {
        float s = 0.f, d = 0.f;
#pragma unroll
        for (int j = 0; j < DIM_H; j++) {
            s += Wsrc[k * DIM_H + j] * atts[j];
            d += Wdst[k * DIM_H + j] * attd[j];
        }
        g_wa_src[k] = s;
        g_wa_dst[k] = d;
    }
}

// ---------------------------------------------------------------------------
// h_src = x @ W_src ; a_src = x @ wa_src ; a_dst = x @ wa_dst
__global__ __launch_bounds__(128, 4) void proj_kernel(const float* __restrict__ x,
                                                      const float* __restrict__ Wsrc) {
    __shared__ float Xs[32][129];
    __shared__ __align__(16) float Ws_s[32][64];
    __shared__ float was_s[32], wad_s[32];

    int tx = threadIdx.x;
    int node0 = blockIdx.x * 128;
    int fg = (tx >> 2) & 7;
    int ng = (tx & 3) + ((tx >> 5) << 2);

    float acc[8][8];
#pragma unroll
    for (int i = 0; i < 8; i++)
#pragma unroll
        for (int j = 0; j < 8; j++) acc[i][j] = 0.f;
    float as = 0.f, ad = 0.f;

    for (int kc = 0; kc < IN_FEAT / 32; kc++) {
        __syncthreads();
#pragma unroll
        for (int i = tx; i < 1024; i += 128) {
            int nd = i >> 3, kq = i & 7;
            int row = node0 + nd; if (row >= N_NODES) row = N_NODES - 1;
            float4 v = ((const float4*)(x + (size_t)row * IN_FEAT + kc * 32))[kq];
            Xs[kq * 4 + 0][nd] = v.x;
            Xs[kq * 4 + 1][nd] = v.y;
            Xs[kq * 4 + 2][nd] = v.z;
            Xs[kq * 4 + 3][nd] = v.w;
        }
        const float4* w4 = (const float4*)(Wsrc + kc * 32 * 64);
        float4* ws4 = (float4*)&Ws_s[0][0];
#pragma unroll
        for (int i = tx; i < 512; i += 128) ws4[i] = w4[i];
        if (tx < 32) was_s[tx] = g_wa_src[kc * 32 + tx];
        else if (tx < 64) wad_s[tx - 32] = g_wa_dst[kc * 32 + tx - 32];
        __syncthreads();

#pragma unroll
        for (int k = 0; k < 32; k++) {
            float xv = Xs[k][tx];
            as += xv * was_s[k];
            ad += xv * wad_s[k];
        }

#pragma unroll
        for (int k = 0; k < 32; k++) {
            float xv[8];
#pragma unroll
            for (int i = 0; i < 8; i++) xv[i] = Xs[k][ng * 8 + i];
            float4 w0 = ((const float4*)&Ws_s[k][0])[fg * 2 + 0];
            float4 w1 = ((const float4*)&Ws_s[k][0])[fg * 2 + 1];
            float wv[8] = {w0.x, w0.y, w0.z, w0.w, w1.x, w1.y, w1.z, w1.w};
#pragma unroll
            for (int i = 0; i < 8; i++)
#pragma unroll
                for (int j = 0; j < 8; j++) acc[i][j] += xv[i] * wv[j];
        }
    }

    int nmax = N_NODES - node0;
#pragma unroll
    for (int i = 0; i < 8; i++) {
        int nd = ng * 8 + i;
        if (nd < nmax) {
            float4* o = (float4*)(g_h_src + (size_t)(node0 + nd) * DIM_H + fg * 8);
            float4 v0 = {acc[i][0], acc[i][1], acc[i][2], acc[i][3]};
            float4 v1 = {acc[i][4], acc[i][5], acc[i][6], acc[i][7]};
            o[0] = v0; o[1] = v1;
        }
    }
    if (tx < nmax) {
        g_a_src[node0 + tx] = as;
        g_a_dst[node0 + tx] = ad;
    }
}

// ---------------------------------------------------------------------------
// pass 1: histogram of dst; atomic return value = within-segment slot
__global__ void hist_kernel(const int* __restrict__ e32) {
    int i = blockIdx.x * blockDim.x + threadIdx.x;
    if (i >= N_EDGES) return;
    int d = load_dst(e32, i, g_is64);
    g_pos[i] = atomicAdd(&g_cnt[d], 1);
}

// pass 2a: per-block exclusive scan (coalesced) + block sums
__global__ __launch_bounds__(SCAN_B) void scan_up_kernel() {
    __shared__ int sm[SCAN_B];
    int t = threadIdx.x;
    int idx = blockIdx.x * SCAN_B + t;
    int v = (idx < N_NODES) ? g_cnt[idx] : 0;
    sm[t] = v;
    __syncthreads();
#pragma unroll
    for (int off = 1; off < SCAN_B; off <<= 1) {
        int u = (t >= off) ? sm[t - off] : 0;
        __syncthreads();
        sm[t] += u;
        __syncthreads();
    }
    if (idx < N_NODES) g_rowptr[idx] = sm[t] - v;   // exclusive, block-local
    if (t == SCAN_B - 1) g_bsum[blockIdx.x] = sm[t];
}

// pass 2b: per-block offset from warp-reduce over g_bsum, then add (fused)
__global__ __launch_bounds__(SCAN_B) void scan_add_kernel() {
    __shared__ int s_off;
    int t = threadIdx.x;
    int b = blockIdx.x;
    if (t < 32) {
        int acc = 0;
        for (int i = t; i < NB_SCAN; i += 32)
            if (i < b) acc += g_bsum[i];
#pragma unroll
        for (int o = 16; o; o >>= 1) acc += __shfl_down_sync(0xFFFFFFFFu, acc, o);
        if (t == 0) s_off = acc;
    }
    __syncthreads();
    int off = s_off;
    int idx = b * SCAN_B + t;
    if (idx < N_NODES) g_rowptr[idx] += off;
    if (b == NB_SCAN - 1 && t == 0)
        g_rowptr[N_NODES] = off + g_bsum[NB_SCAN - 1];   // total = N_EDGES
}

// pass 3: bin edges into CSR order (no atomics; slot from hist)
__global__ void bin_kernel(const int* __restrict__ e32) {
    int i = blockIdx.x * blockDim.x + threadIdx.x;
    if (i >= N_EDGES) return;
    int is64 = g_is64;
    int s = load_src(e32, i, is64);
    int d = load_dst(e32, i, is64);
    float e = g_a_src[s] + g_a_dst[d];
    e = e > 0.f ? e : 0.2f * e;
    float ex = __expf(e);
    float2 rec = {__int_as_float(s), ex};
    g_rec[g_rowptr[d] + g_pos[i]] = rec;
}

// pass 4: per-dst gather reduction (no atomics):
// agg[d] = (sum_j eexp_j * h_src[s_j]) / (sum_j eexp_j)
__global__ __launch_bounds__(256) void gather_kernel() {
    int node = (blockIdx.x * blockDim.x + threadIdx.x) >> 5;
    int lane = threadIdx.x & 31;
    if (node >= N_NODES) return;
    int beg = g_rowptr[node];
    int end = g_rowptr[node + 1];

    float acc0 = 0.f, acc1 = 0.f, denom = 0.f;
    for (int base = beg; base < end; base += 32) {
        int n = min(32, end - base);
        float2 rec = (lane < n) ? g_rec[base + lane] : make_float2(0.f, 0.f);
        for (int j = 0; j < n; j++) {
            float ex = __shfl_sync(0xFFFFFFFFu, rec.y, j);
            int   s  = __shfl_sync(0xFFFFFFFFu, __float_as_int(rec.x), j);
            const float* hp = g_h_src + (size_t)s * DIM_H;
            denom += ex;
            acc0 += ex * hp[lane];
            acc1 += ex * hp[32 + lane];
        }
    }
    float inv = (end > beg) ? (1.f / denom) : 0.f;
    g_agg[(size_t)node * DIM_H + lane]      = acc0 * inv;
    g_agg[(size_t)node * DIM_H + 32 + lane] = acc1 * inv;
}

// ---------------------------------------------------------------------------
// out = relu(agg + bias_conv) @ W_lin + b_lin
__global__ __launch_bounds__(128, 4) void out_kernel(const float* __restrict__ Wlin,
                                                     const float* __restrict__ bias_conv,
                                                     const float* __restrict__ blin,
                                                     float* __restrict__ out) {
    __shared__ float Hs[32][129];
    __shared__ __align__(16) float Ws_s[32][64];
    __shared__ float bc_s[32], bl_s[64];

    int tx = threadIdx.x;
    int node0 = blockIdx.x * 128;
    int fg = (tx >> 2) & 7;
    int ng = (tx & 3) + ((tx >> 5) << 2);

    if (tx < 64) bl_s[tx] = blin[tx];

    float acc[8][8];
#pragma unroll
    for (int i = 0; i < 8; i++)
#pragma unroll
        for (int j = 0; j < 8; j++) acc[i][j] = 0.f;

    for (int kc = 0; kc < DIM_H / 32; kc++) {
        __syncthreads();
        if (tx < 32) bc_s[tx] = bias_conv[kc * 32 + tx];
        __syncthreads();
#pragma unroll
        for (int i = tx; i < 1024; i += 128) {
            int nd = i >> 3, kq = i & 7;
            int row = node0 + nd; if (row >= N_NODES) row = N_NODES - 1;
            float4 v = ((const float4*)(g_agg + (size_t)row * DIM_H + kc * 32))[kq];
            float h0 = v.x + bc_s[kq * 4 + 0];
            float h1 = v.y + bc_s[kq * 4 + 1];
            float h2 = v.z + bc_s[kq * 4 + 2];
            float h3 = v.w + bc_s[kq * 4 + 3];
            Hs[kq * 4 + 0][nd] = h0 > 0.f ? h0 : 0.f;
            Hs[kq * 4 + 1][nd] = h1 > 0.f ? h1 : 0.f;
            Hs[kq * 4 + 2][nd] = h2 > 0.f ? h2 : 0.f;
            Hs[kq * 4 + 3][nd] = h3 > 0.f ? h3 : 0.f;
        }
        const float4* w4 = (const float4*)(Wlin + kc * 32 * 64);
        float4* ws4 = (float4*)&Ws_s[0][0];
#pragma unroll
        for (int i = tx; i < 512; i += 128) ws4[i] = w4[i];
        __syncthreads();

#pragma unroll
        for (int k = 0; k < 32; k++) {
            float hv[8];
#pragma unroll
            for (int i = 0; i < 8; i++) hv[i] = Hs[k][ng * 8 + i];
            float4 w0 = ((const float4*)&Ws_s[k][0])[fg * 2 + 0];
            float4 w1 = ((const float4*)&Ws_s[k][0])[fg * 2 + 1];
            float wv[8] = {w0.x, w0.y, w0.z, w0.w, w1.x, w1.y, w1.z, w1.w};
#pragma unroll
            for (int i = 0; i < 8; i++)
#pragma unroll
                for (int j = 0; j < 8; j++) acc[i][j] += hv[i] * wv[j];
        }
    }

    int nmax = N_NODES - node0;
#pragma unroll
    for (int i = 0; i < 8; i++) {
        int nd = ng * 8 + i;
        if (nd < nmax) {
            float4* o = (float4*)(out + (size_t)(node0 + nd) * DIM_OUT + fg * 8);
            float4 v0 = {acc[i][0] + bl_s[fg * 8 + 0], acc[i][1] + bl_s[fg * 8 + 1],
                         acc[i][2] + bl_s[fg * 8 + 2], acc[i][3] + bl_s[fg * 8 + 3]};
            float4 v1 = {acc[i][4] + bl_s[fg * 8 + 4], acc[i][5] + bl_s[fg * 8 + 5],
                         acc[i][6] + bl_s[fg * 8 + 6], acc[i][7] + bl_s[fg * 8 + 7]};
            o[0] = v0; o[1] = v1;
        }
    }
}

// ---------------------------------------------------------------------------
extern "C" void kernel_launch(void* const* d_in, const int* in_sizes, int n_in,
                              void* d_out, int out_size) {
    const float* x     = (const float*)d_in[0];
    const int*   e32   = (const int*)d_in[1];
    const float* Wsrc  = (const float*)d_in[2];
    const float* Wdst  = (const float*)d_in[3];
    const float* atts  = (const float*)d_in[4];
    const float* attd  = (const float*)d_in[5];
    const float* bconv = (const float*)d_in[6];
    const float* Wlin  = (const float*)d_in[7];
    const float* blin  = (const float*)d_in[8];
    float*       out   = (float*)d_out;

    // streams/events created once, on the first (non-captured) call
    static cudaStream_t sB = nullptr;
    static cudaEvent_t evFork = nullptr, evJoin = nullptr;
    if (!sB) {
        cudaStreamCreateWithFlags(&sB, cudaStreamNonBlocking);
        cudaEventCreateWithFlags(&evFork, cudaEventDisableTiming);
        cudaEventCreateWithFlags(&evJoin, cudaEventDisableTiming);
    }

    void* cnt_ptr = nullptr;
    cudaGetSymbolAddress(&cnt_ptr, g_cnt);

    const int NODE_BLOCKS = (N_NODES + 127) / 128;   // 391
    const int EDGE_BLOCKS = (N_EDGES + 255) / 256;   // 3125

    // stream 0: prep, then fork
    prep_kernel<<<1, 256>>>(e32, Wsrc, Wdst, atts, attd);
    cudaEventRecord(evFork, 0);
    cudaStreamWaitEvent(sB, evFork, 0);

    // stream B: edge indexing chain (independent of proj)
    cudaMemsetAsync(cnt_ptr, 0, (size_t)N_NODES * sizeof(int), sB);
    hist_kernel<<<EDGE_BLOCKS, 256, 0, sB>>>(e32);
    scan_up_kernel<<<NB_SCAN, SCAN_B, 0, sB>>>();
    scan_add_kernel<<<NB_SCAN, SCAN_B, 0, sB>>>();
    cudaEventRecord(evJoin, sB);

    // stream 0: big projection GEMM overlaps stream B
    proj_kernel<<<NODE_BLOCKS, 128>>>(x, Wsrc);

    // join, then dependent tail
    cudaStreamWaitEvent(0, evJoin, 0);
    bin_kernel<<<EDGE_BLOCKS, 256>>>(e32);
    gather_kernel<<<(N_NODES * 32 + 255) / 256, 256>>>();
    out_kernel<<<NODE_BLOCKS, 128>>>(Wlin, bconv, blin, out);
}